// round 5
// baseline (speedup 1.0000x reference)
#include <cuda_runtime.h>
#include <math.h>

#define NB 64
#define NT 12
#define SAMP 768
#define NN 512
#define HH 64

// ---------------- static device scratch (no allocations allowed) ----------------
__device__ __align__(128) float g_A [NN*NN];
__device__ __align__(128) float g_S2[NN*NN];
__device__ float g_pk[NB*HH];
__device__ float g_pv[NB*HH];
__device__ float g_pq[SAMP*HH];
__device__ __align__(128) float g_X1[SAMP*NN*HH];      // de_input
__device__ __align__(128) float g_X2[SAMP*NN*HH];      // z * de_input
__device__ __align__(128) float g_RG[SAMP*NN*HH];      // r gate
__device__ __align__(128) float g_P [2*SAMP*NN*HH];    // [A@X , S2@X]
__device__ __align__(128) float g_W1[SAMP*192*128];    // per-sample gcn1 weights (rows i=1..64, k-major)
__device__ __align__(128) float g_W2[SAMP*192*64];
__device__ float g_B1[SAMP*128];
__device__ float g_B2[SAMP*64];

// ---------------- packed f32x2 helpers ----------------
__device__ __forceinline__ void fma2(unsigned long long &acc, unsigned long long a, unsigned long long b) {
    asm("fma.rn.f32x2 %0, %1, %2, %0;" : "+l"(acc) : "l"(a), "l"(b));
}
__device__ __forceinline__ unsigned long long pk2(float x, float y) {
    unsigned long long r; asm("mov.b64 %0, {%1, %2};" : "=l"(r) : "f"(x), "f"(y)); return r;
}
__device__ __forceinline__ float2 upk2(unsigned long long v) {
    float2 f; asm("mov.b64 {%0, %1}, %2;" : "=f"(f.x), "=f"(f.y) : "l"(v)); return f;
}
__device__ __forceinline__ float sigm(float x) { return 1.f/(1.f + expf(-x)); }

// ---------------- A = row-softmax(relu(E E^T)) ----------------
__global__ void k_A(const float* __restrict__ E) {
    __shared__ float Es[NN*17];
    __shared__ float row[NN];
    __shared__ float red[128];
    int tid = threadIdx.x;
    for (int p = tid; p < NN*16; p += 128) { int m = p >> 4, i = p & 15; Es[m*17+i] = E[p]; }
    __syncthreads();
    int n = blockIdx.x;
    float e[16];
#pragma unroll
    for (int i = 0; i < 16; i++) e[i] = Es[n*17+i];
    float lmax = -1e30f;
    for (int m = tid; m < NN; m += 128) {
        float d = 0.f;
#pragma unroll
        for (int i = 0; i < 16; i++) d += e[i]*Es[m*17+i];
        d = fmaxf(d, 0.f);
        row[m] = d;
        lmax = fmaxf(lmax, d);
    }
    red[tid] = lmax; __syncthreads();
    for (int s = 64; s > 0; s >>= 1) { if (tid < s) red[tid] = fmaxf(red[tid], red[tid+s]); __syncthreads(); }
    float gmax = red[0]; __syncthreads();
    float lsum = 0.f;
    for (int m = tid; m < NN; m += 128) { float v = expf(row[m]-gmax); row[m] = v; lsum += v; }
    red[tid] = lsum; __syncthreads();
    for (int s = 64; s > 0; s >>= 1) { if (tid < s) red[tid] += red[tid+s]; __syncthreads(); }
    float inv = 1.f/red[0];
    for (int m = tid; m < NN; m += 128) g_A[n*NN+m] = row[m]*inv;
}

// ---------------- S2 = 2*A@A - I ----------------
__global__ void __launch_bounds__(256) k_S2() {
    __shared__ float As_[64][17];
    __shared__ float Bs_[16][64];
    int tid = threadIdx.x;
    int tx = tid & 15, ty = tid >> 4;
    int rb = blockIdx.y*64, cb = blockIdx.x*64;
    float acc[4][4] = {};
    for (int k0 = 0; k0 < NN; k0 += 16) {
        for (int p = tid; p < 1024; p += 256) { int r = p >> 4, kk = p & 15; As_[r][kk] = g_A[(rb+r)*NN + k0+kk]; }
        for (int p = tid; p < 1024; p += 256) { int kk = p >> 6, c = p & 63; Bs_[kk][c] = g_A[(k0+kk)*NN + cb+c]; }
        __syncthreads();
#pragma unroll
        for (int kk = 0; kk < 16; kk++) {
            float a[4], b[4];
#pragma unroll
            for (int i = 0; i < 4; i++) a[i] = As_[ty*4+i][kk];
#pragma unroll
            for (int j = 0; j < 4; j++) b[j] = Bs_[kk][tx*4+j];
#pragma unroll
            for (int i = 0; i < 4; i++)
#pragma unroll
                for (int j = 0; j < 4; j++) acc[i][j] += a[i]*b[j];
        }
        __syncthreads();
    }
    for (int i = 0; i < 4; i++)
        for (int j = 0; j < 4; j++) {
            int r = rb + ty*4+i, c = cb + tx*4+j;
            g_S2[r*NN+c] = 2.f*acc[i][j] - (r == c ? 1.f : 0.f);
        }
}

// ---------------- per-batch STE projections ----------------
__global__ void k_prep(const float* __restrict__ ne1, const float* __restrict__ ne2,
                       const float* __restrict__ Wq, const float* __restrict__ bq,
                       const float* __restrict__ Wk, const float* __restrict__ bk,
                       const float* __restrict__ Wv, const float* __restrict__ bv) {
    int b = blockIdx.x, o = threadIdx.x;
    const float* sp = ne1 + (b*NT + NT-1)*32;
    float ak = bk[o], av = bv[o];
    for (int i = 0; i < 32; i++) { float s = sp[i]; ak += s*Wk[i*64+o]; av += s*Wv[i*64+o]; }
    g_pk[b*64+o] = ak; g_pv[b*64+o] = av;
    for (int t = 0; t < NT; t++) {
        const float* sq = ne2 + (b*NT+t)*32;
        float aq = bq[o];
        for (int i = 0; i < 32; i++) aq += sq[i]*Wq[i*64+o];
        g_pq[(b*NT+t)*64 + o] = aq;
    }
}

// ---------------- fused attention -> de_input (g_X1) ----------------
__global__ void __launch_bounds__(256) k_de(const float* __restrict__ hn,
                                            const float* __restrict__ Wq, const float* __restrict__ Wk,
                                            const float* __restrict__ Wv, const float* __restrict__ taw,
                                            const float* __restrict__ tab) {
    __shared__ float pqs[NT*64];
    __shared__ float Xs[4][64], ks[4][64], vs[4][64], xqs[4][64];
    __shared__ float at[4][96];
    int tid = threadIdx.x;
    int b = blockIdx.y;
    int g = tid >> 6, o = tid & 63;
    for (int p = tid; p < NT*64; p += 256) pqs[p] = g_pq[b*NT*64 + p];
    int n = blockIdx.x*4 + g;
    Xs[g][o] = hn[(b*NN + n)*64 + o];
    __syncthreads();
    float ko = g_pk[b*64+o], vo = g_pv[b*64+o], xo = 0.f, ba = tab[o];
    for (int i = 0; i < 64; i++) {
        float x = Xs[g][i];
        ko += x*Wk[(32+i)*64+o];
        vo += x*Wv[(32+i)*64+o];
        xo += x*Wq[(32+i)*64+o];
        ba += x*taw[i*64+o];
    }
    ko = fmaxf(ko, 0.f); vo = fmaxf(vo, 0.f);
    ks[g][o] = ko; vs[g][o] = vo; xqs[g][o] = xo;
    __syncthreads();
    for (int idx = o; idx < 96; idx += 64) {
        int t = idx >> 3, d = idx & 7;
        float a = 0.f;
#pragma unroll
        for (int c = 0; c < 8; c++) {
            int ch = d*8+c;
            a += fmaxf(pqs[t*64+ch] + xqs[g][ch], 0.f) * ks[g][ch];
        }
        at[g][t*8+d] = a;
    }
    __syncthreads();
    if (o < 8) {
        float m = -1e30f;
        for (int t = 0; t < NT; t++) m = fmaxf(m, at[g][t*8+o]);
        float s = 0.f, ev[NT];
        for (int t = 0; t < NT; t++) { ev[t] = expf(at[g][t*8+o]-m); s += ev[t]; }
        float inv = 1.f/s;
        for (int t = 0; t < NT; t++) at[g][t*8+o] = ev[t]*inv;
    }
    __syncthreads();
    float vw[8];
#pragma unroll
    for (int d = 0; d < 8; d++) {
        float a = 0.f;
#pragma unroll
        for (int c = 0; c < 8; c++) a += vs[g][d*8+c]*taw[4096 + (d*8+c)*64 + o];
        vw[d] = a;
    }
    for (int t = 0; t < NT; t++) {
        float val = ba;
#pragma unroll
        for (int d = 0; d < 8; d++) val += at[g][t*8+d]*vw[d];
        g_X1[((b*NT+t)*NN + n)*64 + o] = val;
    }
}

// ---------------- per-sample weights: W[bt] = temb @ wp + w (rows i=1..64 only) ----------------
__global__ void __launch_bounds__(256) k_wcomp(const float* __restrict__ ne2, const float* __restrict__ wp,
                                               const float* __restrict__ w0, int OC, int which) {
    float* out = which ? g_W2 : g_W1;
    __shared__ float ts[4][32];
    int tid = threadIdx.x;
    int bt0 = blockIdx.x*4;
    for (int p = tid; p < 128; p += 256) { int j = p >> 5, d = p & 31; ts[j][d] = ne2[(bt0+j)*32 + d]; }
    __syncthreads();
    int tot = 192*OC;
    int stride = 195*OC;          // 3*65*OC, per-d stride in wp
    for (int idx = tid; idx < tot; idx += 256) {
        int r = idx / OC, o = idx - r*OC;
        int k = r >> 6, i = (r & 63) + 1;
        const float* wpp = wp + (k*65 + i)*OC + o;
        float base = w0[(k*65 + i)*OC + o];
        float a0 = base, a1 = base, a2 = base, a3 = base;
        for (int d = 0; d < 32; d++) {
            float gv = wpp[d*stride];
            a0 += ts[0][d]*gv; a1 += ts[1][d]*gv; a2 += ts[2][d]*gv; a3 += ts[3][d]*gv;
        }
        int ob = (bt0*192 + r)*OC + o;
        out[ob] = a0;
        out[ob + 192*OC] = a1;
        out[ob + 2*192*OC] = a2;
        out[ob + 3*192*OC] = a3;
    }
}

// ---------------- per-sample bias vectors ----------------
__global__ void k_bvec(const float* __restrict__ ne2, const float* __restrict__ gbp, const float* __restrict__ gb,
                       const float* __restrict__ ubp, const float* __restrict__ ub) {
    int bt = blockIdx.x, o = threadIdx.x;   // 128 threads
    const float* te = ne2 + bt*32;
    float a = gb[o];
    for (int d = 0; d < 32; d++) a += te[d]*gbp[d*128+o];
    g_B1[bt*128+o] = a;
    if (o < 64) {
        float b2 = ub[o];
        for (int d = 0; d < 32; d++) b2 += te[d]*ubp[d*64+o];
        g_B2[bt*64+o] = b2;
    }
}

// ---------------- batched S@X (f32x2 microkernel): P[z][bt] = S_z @ X[bt] ----------------
__global__ void __launch_bounds__(256) k_sgemm(int pass) {
    __shared__ float As_[8][132];
    __shared__ float Bs_[8][64];
    int tid = threadIdx.x;
    int bt = blockIdx.y;
    int nbase = blockIdx.x*128;
    const float* S = blockIdx.z ? g_S2 : g_A;
    float* out = g_P + (blockIdx.z*SAMP + bt)*NN*HH;
    const float* Xb = (pass ? g_X2 : g_X1) + bt*NN*HH;
    int tx = tid & 15, ty = tid >> 4;
    unsigned long long acc[8][2];
#pragma unroll
    for (int i = 0; i < 8; i++) { acc[i][0] = 0ull; acc[i][1] = 0ull; }
    int ln = tid >> 1, lh = tid & 1;
    int lkk = tid >> 5, lc = (tid & 31)*2;
    for (int m0 = 0; m0 < NN; m0 += 8) {
        float4 fa = *(const float4*)(S + (nbase+ln)*NN + m0 + lh*4);
        As_[lh*4+0][ln] = fa.x; As_[lh*4+1][ln] = fa.y; As_[lh*4+2][ln] = fa.z; As_[lh*4+3][ln] = fa.w;
        *(float2*)&Bs_[lkk][lc] = *(const float2*)(Xb + (m0+lkk)*64 + lc);
        __syncthreads();
#pragma unroll
        for (int kk = 0; kk < 8; kk++) {
            unsigned long long b0 = *(const unsigned long long*)&Bs_[kk][tx*4];
            unsigned long long b1 = *(const unsigned long long*)&Bs_[kk][tx*4+2];
#pragma unroll
            for (int i = 0; i < 8; i++) {
                float a = As_[kk][ty*8+i];
                unsigned long long ap = pk2(a, a);
                fma2(acc[i][0], ap, b0);
                fma2(acc[i][1], ap, b1);
            }
        }
        __syncthreads();
    }
#pragma unroll
    for (int i = 0; i < 8; i++) {
        float2 p0 = upk2(acc[i][0]), p1 = upk2(acc[i][1]);
        *(float4*)(out + (nbase + ty*8 + i)*64 + tx*4) = make_float4(p0.x, p0.y, p1.x, p1.y);
    }
}

// ---------------- gcn1 contraction + gate epilogue -> X2, RG ----------------
__global__ void __launch_bounds__(256) k_gcn1() {
    __shared__ float As_[8][132];
    __shared__ float Bs_[8][64];
    int tid = threadIdx.x;
    int bt = blockIdx.y;
    int nt = blockIdx.x >> 1, ot = blockIdx.x & 1;
    int nbase = nt*128, ob = ot*64;
    int tx = tid & 15, ty = tid >> 4;
    unsigned long long acc[8][2];
#pragma unroll
    for (int i = 0; i < 8; i++) { acc[i][0] = 0ull; acc[i][1] = 0ull; }
    int ln = tid >> 1, lh = tid & 1;
    int lkk = tid >> 5, lc = (tid & 31)*2;
    const float* W = g_W1 + bt*192*128;
    for (int m0 = 0; m0 < 192; m0 += 8) {
        int src = m0 >> 6;
        const float* Xs = (src == 0 ? g_X1 : g_P + (src-1)*SAMP*NN*HH) + bt*NN*HH;
        int c0 = (m0 & 63) + lh*4;
        float4 fa = *(const float4*)(Xs + (nbase+ln)*64 + c0);
        As_[lh*4+0][ln] = fa.x; As_[lh*4+1][ln] = fa.y; As_[lh*4+2][ln] = fa.z; As_[lh*4+3][ln] = fa.w;
        *(float2*)&Bs_[lkk][lc] = *(const float2*)(W + (m0+lkk)*128 + ob + lc);
        __syncthreads();
#pragma unroll
        for (int kk = 0; kk < 8; kk++) {
            unsigned long long b0 = *(const unsigned long long*)&Bs_[kk][tx*4];
            unsigned long long b1 = *(const unsigned long long*)&Bs_[kk][tx*4+2];
#pragma unroll
            for (int i = 0; i < 8; i++) {
                float a = As_[kk][ty*8+i];
                unsigned long long ap = pk2(a, a);
                fma2(acc[i][0], ap, b0);
                fma2(acc[i][1], ap, b1);
            }
        }
        __syncthreads();
    }
    const float* bv = g_B1 + bt*128 + ob;
    float b0v = bv[tx*4+0], b1v = bv[tx*4+1], b2v = bv[tx*4+2], b3v = bv[tx*4+3];
#pragma unroll
    for (int i = 0; i < 8; i++) {
        int n = nbase + ty*8 + i;
        int idx = (bt*NN + n)*64 + tx*4;
        float2 p0 = upk2(acc[i][0]), p1 = upk2(acc[i][1]);
        float s0 = sigm(p0.x + b0v), s1 = sigm(p0.y + b1v);
        float s2 = sigm(p1.x + b2v), s3 = sigm(p1.y + b3v);
        if (ot == 0) {
            float4 de = *(const float4*)(g_X1 + idx);
            *(float4*)(g_X2 + idx) = make_float4(s0*de.x, s1*de.y, s2*de.z, s3*de.w);
        } else {
            *(float4*)(g_RG + idx) = make_float4(s0, s1, s2, s3);
        }
    }
}

// ---------------- gcn2 contraction + GRU + output projection ----------------
__global__ void __launch_bounds__(256) k_gcn2(const float* __restrict__ ow, const float* __restrict__ obb,
                                              float* __restrict__ out) {
    __shared__ float As_[8][132];
    __shared__ float Bs_[8][64];
    int tid = threadIdx.x;
    int bt = blockIdx.y;
    int t = bt % 12;
    int nbase = blockIdx.x*128;
    int tx = tid & 15, ty = tid >> 4;
    unsigned long long acc[8][2];
#pragma unroll
    for (int i = 0; i < 8; i++) { acc[i][0] = 0ull; acc[i][1] = 0ull; }
    int ln = tid >> 1, lh = tid & 1;
    int lkk = tid >> 5, lc = (tid & 31)*2;
    const float* W = g_W2 + bt*192*64;
    for (int m0 = 0; m0 < 192; m0 += 8) {
        int src = m0 >> 6;
        const float* Xs = (src == 0 ? g_X2 : g_P + (src-1)*SAMP*NN*HH) + bt*NN*HH;
        int c0 = (m0 & 63) + lh*4;
        float4 fa = *(const float4*)(Xs + (nbase+ln)*64 + c0);
        As_[lh*4+0][ln] = fa.x; As_[lh*4+1][ln] = fa.y; As_[lh*4+2][ln] = fa.z; As_[lh*4+3][ln] = fa.w;
        *(float2*)&Bs_[lkk][lc] = *(const float2*)(W + (m0+lkk)*64 + lc);
        __syncthreads();
#pragma unroll
        for (int kk = 0; kk < 8; kk++) {
            unsigned long long b0 = *(const unsigned long long*)&Bs_[kk][tx*4];
            unsigned long long b1 = *(const unsigned long long*)&Bs_[kk][tx*4+2];
#pragma unroll
            for (int i = 0; i < 8; i++) {
                float a = As_[kk][ty*8+i];
                unsigned long long ap = pk2(a, a);
                fma2(acc[i][0], ap, b0);
                fma2(acc[i][1], ap, b1);
            }
        }
        __syncthreads();
    }
    const float* bv = g_B2 + bt*64;
    float bb[4], wv[4];
#pragma unroll
    for (int j = 0; j < 4; j++) { bb[j] = bv[tx*4+j]; wv[j] = ow[t*64 + tx*4 + j]; }
#pragma unroll
    for (int i = 0; i < 8; i++) {
        int n = nbase + ty*8 + i;
        int idx = (bt*NN + n)*64 + tx*4;
        float4 de = *(const float4*)(g_X1 + idx);
        float4 rg = *(const float4*)(g_RG + idx);
        float2 p0 = upk2(acc[i][0]), p1 = upk2(acc[i][1]);
        float y[4] = {p0.x, p0.y, p1.x, p1.y};
        float d4[4] = {de.x, de.y, de.z, de.w};
        float r4[4] = {rg.x, rg.y, rg.z, rg.w};
        float part = 0.f;
#pragma unroll
        for (int j = 0; j < 4; j++) {
            float hc = tanhf(y[j] + bb[j]);
            float st = r4[j]*d4[j] + (1.f - r4[j])*hc;
            part += st*wv[j];
        }
        for (int off = 8; off > 0; off >>= 1)
            part += __shfl_down_sync(0xffffffffu, part, off, 16);
        if (tx == 0) out[bt*NN + n] = part + obb[t];
    }
}

extern "C" void kernel_launch(void* const* d_in, const int* in_sizes, int n_in,
                              void* d_out, int out_size) {
    const float* hn  = (const float*)d_in[2];
    const float* ne1 = (const float*)d_in[3];
    const float* ne2 = (const float*)d_in[4];
    const float* E   = (const float*)d_in[5];
    const float* Wq  = (const float*)d_in[6];  const float* bq = (const float*)d_in[7];
    const float* Wk  = (const float*)d_in[8];  const float* bk = (const float*)d_in[9];
    const float* Wv  = (const float*)d_in[10]; const float* bv = (const float*)d_in[11];
    const float* taw = (const float*)d_in[12]; const float* tab = (const float*)d_in[13];
    const float* gwp = (const float*)d_in[14]; const float* gw = (const float*)d_in[15];
    const float* gbp = (const float*)d_in[16]; const float* gb = (const float*)d_in[17];
    const float* uwp = (const float*)d_in[18]; const float* uw = (const float*)d_in[19];
    const float* ubp = (const float*)d_in[20]; const float* ub = (const float*)d_in[21];
    const float* ow  = (const float*)d_in[22]; const float* ob = (const float*)d_in[23];
    float* out = (float*)d_out;

    k_A<<<512, 128>>>(E);
    k_S2<<<dim3(8, 8), 256>>>();
    k_prep<<<64, 64>>>(ne1, ne2, Wq, bq, Wk, bk, Wv, bv);
    k_de<<<dim3(128, 64), 256>>>(hn, Wq, Wk, Wv, taw, tab);
    k_wcomp<<<192, 256>>>(ne2, gwp, gw, 128, 0);
    k_wcomp<<<192, 256>>>(ne2, uwp, uw, 64, 1);
    k_bvec<<<768, 128>>>(ne2, gbp, gb, ubp, ub);
    k_sgemm<<<dim3(4, 768, 2), 256>>>(0);
    k_gcn1<<<dim3(8, 768), 256>>>();
    k_sgemm<<<dim3(4, 768, 2), 256>>>(1);
    k_gcn2<<<dim3(4, 768), 256>>>(ow, ob, out);
}

// round 6
// speedup vs baseline: 1.3609x; 1.3609x over previous
#include <cuda_runtime.h>
#include <math.h>

#define NB 64
#define NT 12
#define SAMP 768
#define NN 512
#define HH 64

// ---------------- static device scratch (no allocations allowed) ----------------
__device__ __align__(128) float g_A [NN*NN];
__device__ __align__(128) float g_S2[NN*NN];
__device__ float g_pk[NB*HH];
__device__ float g_pv[NB*HH];
__device__ float g_pq[SAMP*HH];
__device__ __align__(128) float g_X1[SAMP*NN*HH];      // de_input
__device__ __align__(128) float g_X2[SAMP*NN*HH];      // z * de_input
__device__ __align__(128) float g_RG[SAMP*NN*HH];      // r gate
__device__ __align__(128) float g_P [2*SAMP*NN*HH];    // [A@X , S2@X]
__device__ __align__(128) float g_W1[SAMP*192*128];    // per-sample gcn1 weights (rows i=1..64, k-major)
__device__ __align__(128) float g_W2[SAMP*192*64];
__device__ float g_B1[SAMP*128];
__device__ float g_B2[SAMP*64];

// ---------------- packed f32x2 helpers ----------------
__device__ __forceinline__ void fma2(unsigned long long &acc, unsigned long long a, unsigned long long b) {
    asm("fma.rn.f32x2 %0, %1, %2, %0;" : "+l"(acc) : "l"(a), "l"(b));
}
__device__ __forceinline__ float2 upk2(unsigned long long v) {
    float2 f; asm("mov.b64 {%0, %1}, %2;" : "=f"(f.x), "=f"(f.y) : "l"(v)); return f;
}
__device__ __forceinline__ float sigm(float x) { return 1.f/(1.f + expf(-x)); }

// ---------------- A = row-softmax(relu(E E^T)) ----------------
__global__ void k_A(const float* __restrict__ E) {
    __shared__ float Es[NN*17];
    __shared__ float row[NN];
    __shared__ float red[128];
    int tid = threadIdx.x;
    for (int p = tid; p < NN*16; p += 128) { int m = p >> 4, i = p & 15; Es[m*17+i] = E[p]; }
    __syncthreads();
    int n = blockIdx.x;
    float e[16];
#pragma unroll
    for (int i = 0; i < 16; i++) e[i] = Es[n*17+i];
    float lmax = -1e30f;
    for (int m = tid; m < NN; m += 128) {
        float d = 0.f;
#pragma unroll
        for (int i = 0; i < 16; i++) d += e[i]*Es[m*17+i];
        d = fmaxf(d, 0.f);
        row[m] = d;
        lmax = fmaxf(lmax, d);
    }
    red[tid] = lmax; __syncthreads();
    for (int s = 64; s > 0; s >>= 1) { if (tid < s) red[tid] = fmaxf(red[tid], red[tid+s]); __syncthreads(); }
    float gmax = red[0]; __syncthreads();
    float lsum = 0.f;
    for (int m = tid; m < NN; m += 128) { float v = expf(row[m]-gmax); row[m] = v; lsum += v; }
    red[tid] = lsum; __syncthreads();
    for (int s = 64; s > 0; s >>= 1) { if (tid < s) red[tid] += red[tid+s]; __syncthreads(); }
    float inv = 1.f/red[0];
    for (int m = tid; m < NN; m += 128) g_A[n*NN+m] = row[m]*inv;
}

// ---------------- S2 = 2*A@A - I ----------------
__global__ void __launch_bounds__(256) k_S2() {
    __shared__ float As_[64][17];
    __shared__ float Bs_[16][64];
    int tid = threadIdx.x;
    int tx = tid & 15, ty = tid >> 4;
    int rb = blockIdx.y*64, cb = blockIdx.x*64;
    float acc[4][4] = {};
    for (int k0 = 0; k0 < NN; k0 += 16) {
        for (int p = tid; p < 1024; p += 256) { int r = p >> 4, kk = p & 15; As_[r][kk] = g_A[(rb+r)*NN + k0+kk]; }
        for (int p = tid; p < 1024; p += 256) { int kk = p >> 6, c = p & 63; Bs_[kk][c] = g_A[(k0+kk)*NN + cb+c]; }
        __syncthreads();
#pragma unroll
        for (int kk = 0; kk < 16; kk++) {
            float a[4], b[4];
#pragma unroll
            for (int i = 0; i < 4; i++) a[i] = As_[ty*4+i][kk];
#pragma unroll
            for (int j = 0; j < 4; j++) b[j] = Bs_[kk][tx*4+j];
#pragma unroll
            for (int i = 0; i < 4; i++)
#pragma unroll
                for (int j = 0; j < 4; j++) acc[i][j] += a[i]*b[j];
        }
        __syncthreads();
    }
    for (int i = 0; i < 4; i++)
        for (int j = 0; j < 4; j++) {
            int r = rb + ty*4+i, c = cb + tx*4+j;
            g_S2[r*NN+c] = 2.f*acc[i][j] - (r == c ? 1.f : 0.f);
        }
}

// ---------------- per-batch STE projections ----------------
__global__ void k_prep(const float* __restrict__ ne1, const float* __restrict__ ne2,
                       const float* __restrict__ Wq, const float* __restrict__ bq,
                       const float* __restrict__ Wk, const float* __restrict__ bk,
                       const float* __restrict__ Wv, const float* __restrict__ bv) {
    int b = blockIdx.x, o = threadIdx.x;
    const float* sp = ne1 + (b*NT + NT-1)*32;
    float ak = bk[o], av = bv[o];
    for (int i = 0; i < 32; i++) { float s = sp[i]; ak += s*Wk[i*64+o]; av += s*Wv[i*64+o]; }
    g_pk[b*64+o] = ak; g_pv[b*64+o] = av;
    for (int t = 0; t < NT; t++) {
        const float* sq = ne2 + (b*NT+t)*32;
        float aq = bq[o];
        for (int i = 0; i < 32; i++) aq += sq[i]*Wq[i*64+o];
        g_pq[(b*NT+t)*64 + o] = aq;
    }
}

// ---------------- fused attention -> de_input (g_X1) ----------------
__global__ void __launch_bounds__(256) k_de(const float* __restrict__ hn,
                                            const float* __restrict__ Wq, const float* __restrict__ Wk,
                                            const float* __restrict__ Wv, const float* __restrict__ taw,
                                            const float* __restrict__ tab) {
    __shared__ float pqs[NT*64];
    __shared__ float Xs[4][64], ks[4][64], vs[4][64], xqs[4][64];
    __shared__ float at[4][96];
    int tid = threadIdx.x;
    int b = blockIdx.y;
    int g = tid >> 6, o = tid & 63;
    for (int p = tid; p < NT*64; p += 256) pqs[p] = g_pq[b*NT*64 + p];
    int n = blockIdx.x*4 + g;
    Xs[g][o] = hn[(b*NN + n)*64 + o];
    __syncthreads();
    float ko = g_pk[b*64+o], vo = g_pv[b*64+o], xo = 0.f, ba = tab[o];
    for (int i = 0; i < 64; i++) {
        float x = Xs[g][i];
        ko += x*Wk[(32+i)*64+o];
        vo += x*Wv[(32+i)*64+o];
        xo += x*Wq[(32+i)*64+o];
        ba += x*taw[i*64+o];
    }
    ko = fmaxf(ko, 0.f); vo = fmaxf(vo, 0.f);
    ks[g][o] = ko; vs[g][o] = vo; xqs[g][o] = xo;
    __syncthreads();
    for (int idx = o; idx < 96; idx += 64) {
        int t = idx >> 3, d = idx & 7;
        float a = 0.f;
#pragma unroll
        for (int c = 0; c < 8; c++) {
            int ch = d*8+c;
            a += fmaxf(pqs[t*64+ch] + xqs[g][ch], 0.f) * ks[g][ch];
        }
        at[g][t*8+d] = a;
    }
    __syncthreads();
    if (o < 8) {
        float m = -1e30f;
        for (int t = 0; t < NT; t++) m = fmaxf(m, at[g][t*8+o]);
        float s = 0.f, ev[NT];
        for (int t = 0; t < NT; t++) { ev[t] = expf(at[g][t*8+o]-m); s += ev[t]; }
        float inv = 1.f/s;
        for (int t = 0; t < NT; t++) at[g][t*8+o] = ev[t]*inv;
    }
    __syncthreads();
    float vw[8];
#pragma unroll
    for (int d = 0; d < 8; d++) {
        float a = 0.f;
#pragma unroll
        for (int c = 0; c < 8; c++) a += vs[g][d*8+c]*taw[4096 + (d*8+c)*64 + o];
        vw[d] = a;
    }
    for (int t = 0; t < NT; t++) {
        float val = ba;
#pragma unroll
        for (int d = 0; d < 8; d++) val += at[g][t*8+d]*vw[d];
        g_X1[((b*NT+t)*NN + n)*64 + o] = val;
    }
}

// ---------------- per-sample weights: W[bt] = temb @ wp + w (rows i=1..64 only) ----------------
__global__ void __launch_bounds__(256) k_wcomp(const float* __restrict__ ne2, const float* __restrict__ wp,
                                               const float* __restrict__ w0, int OC, int which) {
    float* out = which ? g_W2 : g_W1;
    __shared__ float ts[4][32];
    int tid = threadIdx.x;
    int bt0 = blockIdx.x*4;
    for (int p = tid; p < 128; p += 256) { int j = p >> 5, d = p & 31; ts[j][d] = ne2[(bt0+j)*32 + d]; }
    __syncthreads();
    int tot = 192*OC;
    int stride = 195*OC;          // 3*65*OC, per-d stride in wp
    for (int idx = tid; idx < tot; idx += 256) {
        int r = idx / OC, o = idx - r*OC;
        int k = r >> 6, i = (r & 63) + 1;
        const float* wpp = wp + (k*65 + i)*OC + o;
        float base = w0[(k*65 + i)*OC + o];
        float a0 = base, a1 = base, a2 = base, a3 = base;
        for (int d = 0; d < 32; d++) {
            float gv = wpp[d*stride];
            a0 += ts[0][d]*gv; a1 += ts[1][d]*gv; a2 += ts[2][d]*gv; a3 += ts[3][d]*gv;
        }
        int ob = (bt0*192 + r)*OC + o;
        out[ob] = a0;
        out[ob + 192*OC] = a1;
        out[ob + 2*192*OC] = a2;
        out[ob + 3*192*OC] = a3;
    }
}

// ---------------- per-sample bias vectors ----------------
__global__ void k_bvec(const float* __restrict__ ne2, const float* __restrict__ gbp, const float* __restrict__ gb,
                       const float* __restrict__ ubp, const float* __restrict__ ub) {
    int bt = blockIdx.x, o = threadIdx.x;   // 128 threads
    const float* te = ne2 + bt*32;
    float a = gb[o];
    for (int d = 0; d < 32; d++) a += te[d]*gbp[d*128+o];
    g_B1[bt*128+o] = a;
    if (o < 64) {
        float b2 = ub[o];
        for (int d = 0; d < 32; d++) b2 += te[d]*ubp[d*64+o];
        g_B2[bt*64+o] = b2;
    }
}

// ============ improved f32x2 microkernel core ============
// acc pairs span adjacent n-rows (n0 = ty*8+2p, n1 = n0+1), columns strided c = tx + 16*j.
// At[k][n]: transposed A-operand tile; Bd[k][2c]=Bd[k][2c+1]: pre-duplicated B-operand tile.
// Inner loop per k: 4 LDS64 (A pairs, warp-broadcast) + 4 LDS64 (B pairs, consecutive) + 16 FFMA2.

// ---------------- batched S@X: P[z][bt] = S_z @ X[bt] ----------------
__global__ void __launch_bounds__(256) k_sgemm(int pass) {
    __shared__ float At[16][138];
    __shared__ float Bd[16][128];
    int tid = threadIdx.x;
    int bt = blockIdx.y;
    int nbase = blockIdx.x*128;
    const float* S = blockIdx.z ? g_S2 : g_A;
    float* out = g_P + (blockIdx.z*SAMP + bt)*NN*HH;
    const float* Xb = (pass ? g_X2 : g_X1) + bt*NN*HH;
    int tx = tid & 15, ty = tid >> 4;
    int ln = tid >> 1, lh = (tid & 1)*8;
    int bm = tid >> 4, bc = (tid & 15)*4;
    unsigned long long acc[4][4];
#pragma unroll
    for (int p = 0; p < 4; p++)
#pragma unroll
        for (int j = 0; j < 4; j++) acc[p][j] = 0ull;
    for (int m0 = 0; m0 < NN; m0 += 16) {
        const float* srow = S + (nbase+ln)*NN + m0 + lh;
        float4 fa = *(const float4*)srow;
        float4 fb = *(const float4*)(srow + 4);
        At[lh+0][ln]=fa.x; At[lh+1][ln]=fa.y; At[lh+2][ln]=fa.z; At[lh+3][ln]=fa.w;
        At[lh+4][ln]=fb.x; At[lh+5][ln]=fb.y; At[lh+6][ln]=fb.z; At[lh+7][ln]=fb.w;
        float4 xv = *(const float4*)(Xb + (m0+bm)*64 + bc);
        *(float4*)&Bd[bm][bc*2]   = make_float4(xv.x, xv.x, xv.y, xv.y);
        *(float4*)&Bd[bm][bc*2+4] = make_float4(xv.z, xv.z, xv.w, xv.w);
        __syncthreads();
#pragma unroll
        for (int kk = 0; kk < 16; kk++) {
            unsigned long long av[4], bv[4];
#pragma unroll
            for (int p = 0; p < 4; p++) av[p] = *(const unsigned long long*)&At[kk][ty*8 + 2*p];
#pragma unroll
            for (int j = 0; j < 4; j++) bv[j] = *(const unsigned long long*)&Bd[kk][2*tx + 32*j];
#pragma unroll
            for (int p = 0; p < 4; p++)
#pragma unroll
                for (int j = 0; j < 4; j++) fma2(acc[p][j], av[p], bv[j]);
        }
        __syncthreads();
    }
#pragma unroll
    for (int p = 0; p < 4; p++) {
        int n0 = nbase + ty*8 + 2*p;
        float* o0 = out + n0*64 + tx;
#pragma unroll
        for (int j = 0; j < 4; j++) {
            float2 u = upk2(acc[p][j]);
            o0[j*16] = u.x;
            o0[64 + j*16] = u.y;
        }
    }
}

// ---------------- gcn1 contraction + gate epilogue -> X2, RG ----------------
__global__ void __launch_bounds__(256) k_gcn1() {
    __shared__ float At[16][138];
    __shared__ float Bd[16][128];
    int tid = threadIdx.x;
    int bt = blockIdx.y;
    int nt = blockIdx.x >> 1, ot = blockIdx.x & 1;
    int nbase = nt*128, ob = ot*64;
    int tx = tid & 15, ty = tid >> 4;
    int ln = tid >> 1, lh = (tid & 1)*8;
    int bm = tid >> 4, bc = (tid & 15)*4;
    const float* W = g_W1 + bt*192*128;
    unsigned long long acc[4][4];
#pragma unroll
    for (int p = 0; p < 4; p++)
#pragma unroll
        for (int j = 0; j < 4; j++) acc[p][j] = 0ull;
    for (int m0 = 0; m0 < 192; m0 += 16) {
        int src = m0 >> 6;
        const float* Xs = (src == 0 ? g_X1 : g_P + (src-1)*SAMP*NN*HH) + bt*NN*HH;
        int c0 = (m0 & 63) + lh;
        const float* xrow = Xs + (nbase+ln)*64 + c0;
        float4 fa = *(const float4*)xrow;
        float4 fb = *(const float4*)(xrow + 4);
        At[lh+0][ln]=fa.x; At[lh+1][ln]=fa.y; At[lh+2][ln]=fa.z; At[lh+3][ln]=fa.w;
        At[lh+4][ln]=fb.x; At[lh+5][ln]=fb.y; At[lh+6][ln]=fb.z; At[lh+7][ln]=fb.w;
        float4 wv = *(const float4*)(W + (m0+bm)*128 + ob + bc);
        *(float4*)&Bd[bm][bc*2]   = make_float4(wv.x, wv.x, wv.y, wv.y);
        *(float4*)&Bd[bm][bc*2+4] = make_float4(wv.z, wv.z, wv.w, wv.w);
        __syncthreads();
#pragma unroll
        for (int kk = 0; kk < 16; kk++) {
            unsigned long long av[4], bv[4];
#pragma unroll
            for (int p = 0; p < 4; p++) av[p] = *(const unsigned long long*)&At[kk][ty*8 + 2*p];
#pragma unroll
            for (int j = 0; j < 4; j++) bv[j] = *(const unsigned long long*)&Bd[kk][2*tx + 32*j];
#pragma unroll
            for (int p = 0; p < 4; p++)
#pragma unroll
                for (int j = 0; j < 4; j++) fma2(acc[p][j], av[p], bv[j]);
        }
        __syncthreads();
    }
    const float* bvv = g_B1 + bt*128 + ob;
    float bb[4];
#pragma unroll
    for (int j = 0; j < 4; j++) bb[j] = bvv[tx + j*16];
#pragma unroll
    for (int p = 0; p < 4; p++) {
        int n0 = nbase + ty*8 + 2*p;
        int base = (bt*NN + n0)*64 + tx;
#pragma unroll
        for (int j = 0; j < 4; j++) {
            float2 u = upk2(acc[p][j]);
            float s0 = sigm(u.x + bb[j]);
            float s1 = sigm(u.y + bb[j]);
            int i0 = base + j*16, i1 = i0 + 64;
            if (ot == 0) {
                g_X2[i0] = s0 * g_X1[i0];
                g_X2[i1] = s1 * g_X1[i1];
            } else {
                g_RG[i0] = s0;
                g_RG[i1] = s1;
            }
        }
    }
}

// ---------------- gcn2 contraction + GRU + output projection ----------------
__global__ void __launch_bounds__(256) k_gcn2(const float* __restrict__ ow, const float* __restrict__ obb,
                                              float* __restrict__ out) {
    __shared__ float At[16][138];
    __shared__ float Bd[16][128];
    int tid = threadIdx.x;
    int bt = blockIdx.y;
    int t = bt % 12;
    int nbase = blockIdx.x*128;
    int tx = tid & 15, ty = tid >> 4;
    int ln = tid >> 1, lh = (tid & 1)*8;
    int bm = tid >> 4, bc = (tid & 15)*4;
    const float* W = g_W2 + bt*192*64;
    unsigned long long acc[4][4];
#pragma unroll
    for (int p = 0; p < 4; p++)
#pragma unroll
        for (int j = 0; j < 4; j++) acc[p][j] = 0ull;
    for (int m0 = 0; m0 < 192; m0 += 16) {
        int src = m0 >> 6;
        const float* Xs = (src == 0 ? g_X2 : g_P + (src-1)*SAMP*NN*HH) + bt*NN*HH;
        int c0 = (m0 & 63) + lh;
        const float* xrow = Xs + (nbase+ln)*64 + c0;
        float4 fa = *(const float4*)xrow;
        float4 fb = *(const float4*)(xrow + 4);
        At[lh+0][ln]=fa.x; At[lh+1][ln]=fa.y; At[lh+2][ln]=fa.z; At[lh+3][ln]=fa.w;
        At[lh+4][ln]=fb.x; At[lh+5][ln]=fb.y; At[lh+6][ln]=fb.z; At[lh+7][ln]=fb.w;
        float4 wv = *(const float4*)(W + (m0+bm)*64 + bc);
        *(float4*)&Bd[bm][bc*2]   = make_float4(wv.x, wv.x, wv.y, wv.y);
        *(float4*)&Bd[bm][bc*2+4] = make_float4(wv.z, wv.z, wv.w, wv.w);
        __syncthreads();
#pragma unroll
        for (int kk = 0; kk < 16; kk++) {
            unsigned long long av[4], bv[4];
#pragma unroll
            for (int p = 0; p < 4; p++) av[p] = *(const unsigned long long*)&At[kk][ty*8 + 2*p];
#pragma unroll
            for (int j = 0; j < 4; j++) bv[j] = *(const unsigned long long*)&Bd[kk][2*tx + 32*j];
#pragma unroll
            for (int p = 0; p < 4; p++)
#pragma unroll
                for (int j = 0; j < 4; j++) fma2(acc[p][j], av[p], bv[j]);
        }
        __syncthreads();
    }
    const float* bvv = g_B2 + bt*64;
    float bb[4], wv[4];
#pragma unroll
    for (int j = 0; j < 4; j++) { bb[j] = bvv[tx + j*16]; wv[j] = ow[t*64 + tx + j*16]; }
#pragma unroll
    for (int p = 0; p < 4; p++) {
        int n0 = nbase + ty*8 + 2*p;
        int base = (bt*NN + n0)*64 + tx;
        float part0 = 0.f, part1 = 0.f;
#pragma unroll
        for (int j = 0; j < 4; j++) {
            float2 u = upk2(acc[p][j]);
            int i0 = base + j*16, i1 = i0 + 64;
            float de0 = g_X1[i0], rg0 = g_RG[i0];
            float de1 = g_X1[i1], rg1 = g_RG[i1];
            float hc0 = tanhf(u.x + bb[j]);
            float hc1 = tanhf(u.y + bb[j]);
            part0 += (rg0*de0 + (1.f - rg0)*hc0) * wv[j];
            part1 += (rg1*de1 + (1.f - rg1)*hc1) * wv[j];
        }
        for (int off = 8; off > 0; off >>= 1) {
            part0 += __shfl_down_sync(0xffffffffu, part0, off, 16);
            part1 += __shfl_down_sync(0xffffffffu, part1, off, 16);
        }
        if (tx == 0) {
            out[bt*NN + n0]     = part0 + obb[t];
            out[bt*NN + n0 + 1] = part1 + obb[t];
        }
    }
}

extern "C" void kernel_launch(void* const* d_in, const int* in_sizes, int n_in,
                              void* d_out, int out_size) {
    const float* hn  = (const float*)d_in[2];
    const float* ne1 = (const float*)d_in[3];
    const float* ne2 = (const float*)d_in[4];
    const float* E   = (const float*)d_in[5];
    const float* Wq  = (const float*)d_in[6];  const float* bq = (const float*)d_in[7];
    const float* Wk  = (const float*)d_in[8];  const float* bk = (const float*)d_in[9];
    const float* Wv  = (const float*)d_in[10]; const float* bv = (const float*)d_in[11];
    const float* taw = (const float*)d_in[12]; const float* tab = (const float*)d_in[13];
    const float* gwp = (const float*)d_in[14]; const float* gw = (const float*)d_in[15];
    const float* gbp = (const float*)d_in[16]; const float* gb = (const float*)d_in[17];
    const float* uwp = (const float*)d_in[18]; const float* uw = (const float*)d_in[19];
    const float* ubp = (const float*)d_in[20]; const float* ub = (const float*)d_in[21];
    const float* ow  = (const float*)d_in[22]; const float* ob = (const float*)d_in[23];
    float* out = (float*)d_out;

    // order chosen so the 6th launch (ncu -s 5 -c 1) is the dominant k_sgemm
    k_A<<<512, 128>>>(E);
    k_S2<<<dim3(8, 8), 256>>>();
    k_prep<<<64, 64>>>(ne1, ne2, Wq, bq, Wk, bk, Wv, bv);
    k_de<<<dim3(128, 64), 256>>>(hn, Wq, Wk, Wv, taw, tab);
    k_wcomp<<<192, 256>>>(ne2, gwp, gw, 128, 0);
    k_sgemm<<<dim3(4, 768, 2), 256>>>(0);
    k_wcomp<<<192, 256>>>(ne2, uwp, uw, 64, 1);
    k_bvec<<<768, 128>>>(ne2, gbp, gb, ubp, ub);
    k_gcn1<<<dim3(8, 768), 256>>>();
    k_sgemm<<<dim3(4, 768, 2), 256>>>(1);
    k_gcn2<<<dim3(4, 768), 256>>>(ow, ob, out);
}